// round 12
// baseline (speedup 1.0000x reference)
#include <cuda_runtime.h>
#include <cuda_fp16.h>
#include <stdint.h>

#define N_NODES 20000
#define NPAD    20096           // 157 * 128
#define NBLK    157             // NPAD / 128
#define HID     256
#define E_EDGES 640000
#define NH      (N_NODES * HID) // 5,120,000

// ---------------- scratch (device globals; no allocation) ----------------
__device__ int    g_is64;
__device__ int    g_deg[N_NODES];
__device__ int    g_cursor[N_NODES];
__device__ int    g_rowptr[N_NODES + 1];
__device__ int    g_bsum[NBLK];
__device__ int2   g_csr[E_EDGES];       // (src, bitcast(dinv[src]))
__device__ float  g_dinv[N_NODES];
__device__ __half g_h[NPAD * HID];      // fp16 activations (pad rows stay zero)
__device__ __half g_t[NPAD * HID];      // fp16 GEMM output (gather payload)
__device__ __half g_wh1[HID * HID];     // fp16 weights
__device__ __half g_wh2[HID * HID];

// ---------------- mma/ldmatrix/cp.async helpers ----------------
__device__ __forceinline__ void ldsm_x4(uint32_t (&r)[4], uint32_t addr)
{
    asm volatile("ldmatrix.sync.aligned.m8n8.x4.shared.b16 {%0,%1,%2,%3}, [%4];"
        : "=r"(r[0]), "=r"(r[1]), "=r"(r[2]), "=r"(r[3]) : "r"(addr));
}
__device__ __forceinline__ void ldsm_x2_trans(uint32_t (&r)[2], uint32_t addr)
{
    asm volatile("ldmatrix.sync.aligned.m8n8.x2.trans.shared.b16 {%0,%1}, [%2];"
        : "=r"(r[0]), "=r"(r[1]) : "r"(addr));
}
__device__ __forceinline__ void mma16816(float (&c)[4], const uint32_t (&a)[4], const uint32_t (&b)[2])
{
    asm volatile("mma.sync.aligned.m16n8k16.row.col.f32.f16.f16.f32 "
        "{%0,%1,%2,%3}, {%4,%5,%6,%7}, {%8,%9}, {%0,%1,%2,%3};"
        : "+f"(c[0]), "+f"(c[1]), "+f"(c[2]), "+f"(c[3])
        : "r"(a[0]), "r"(a[1]), "r"(a[2]), "r"(a[3]), "r"(b[0]), "r"(b[1]));
}
__device__ __forceinline__ void cp16(uint32_t saddr, const void* g)
{
    asm volatile("cp.async.cg.shared.global [%0], [%1], 16;" :: "r"(saddr), "l"(g));
}

// ---------------- threefry2x32 (JAX-exact) ----------------
__host__ __device__ __forceinline__ void threefry2x32(
    uint32_t k0, uint32_t k1, uint32_t x0, uint32_t x1,
    uint32_t* o0, uint32_t* o1)
{
    uint32_t ks2 = k0 ^ k1 ^ 0x1BD11BDAu;
    x0 += k0; x1 += k1;
#define TF_R(r) { x0 += x1; x1 = (x1 << (r)) | (x1 >> (32 - (r))); x1 ^= x0; }
    TF_R(13) TF_R(15) TF_R(26) TF_R(6)
    x0 += k1; x1 += ks2 + 1u;
    TF_R(17) TF_R(29) TF_R(16) TF_R(24)
    x0 += ks2; x1 += k0 + 2u;
    TF_R(13) TF_R(15) TF_R(26) TF_R(6)
    x0 += k0; x1 += k1 + 3u;
    TF_R(17) TF_R(29) TF_R(16) TF_R(24)
    x0 += k1; x1 += ks2 + 4u;
    TF_R(13) TF_R(15) TF_R(26) TF_R(6)
    x0 += ks2; x1 += k0 + 5u;
#undef TF_R
    *o0 = x0; *o1 = x1;
}

// JAX partitionable threefry: bits32[e] = o0 ^ o1 at counter (0, e);
// keep <=> bit31 == 0; kept values scaled by 1/(1-p) = 2.
__device__ __forceinline__ float apply_dropout(float v, uint32_t k0, uint32_t k1, uint32_t e)
{
    uint32_t o0, o1;
    threefry2x32(k0, k1, 0u, e, &o0, &o1);
    return ((o0 ^ o1) & 0x80000000u) ? 0.0f : 2.0f * v;
}

// ---------------- prep: detect dtype + zero deg/cursor + convert weights ----------
__global__ void prep_kernel(const unsigned int* __restrict__ w,
                            const float* __restrict__ W1,
                            const float* __restrict__ W2)
{
    int b = blockIdx.x;
    if (b < 79) {
        int i = b * 256 + threadIdx.x;
        if (i < N_NODES) { g_deg[i] = 0; g_cursor[i] = 0; }
    } else if (b == 79) {
        if (threadIdx.x < 32) {
            int lane = threadIdx.x;
            int z = (w[4 * lane + 1] == 0u) && (w[4 * lane + 3] == 0u);
            unsigned m = __ballot_sync(0xffffffffu, z);
            if (lane == 0) g_is64 = (m == 0xffffffffu);
        }
    } else {
        int i = ((b - 80) * 256 + threadIdx.x) * 4;
        float4 v1 = *(const float4*)(W1 + i);
        float4 v2 = *(const float4*)(W2 + i);
        __half2 a1 = __floats2half2_rn(v1.x, v1.y), b1 = __floats2half2_rn(v1.z, v1.w);
        __half2 a2 = __floats2half2_rn(v2.x, v2.y), b2 = __floats2half2_rn(v2.z, v2.w);
        *(uint2*)(g_wh1 + i) = make_uint2(*(uint32_t*)&a1, *(uint32_t*)&b1);
        *(uint2*)(g_wh2 + i) = make_uint2(*(uint32_t*)&a2, *(uint32_t*)&b2);
    }
}

__global__ void convert_kernel(const void* __restrict__ ei)
{
    int e = blockIdx.x * blockDim.x + threadIdx.x;
    if (e >= E_EDGES) return;
    int d;
    if (g_is64) d = (int)((const long long*)ei)[E_EDGES + e];
    else        d = ((const int*)ei)[E_EDGES + e];
    atomicAdd(&g_deg[d], 1);
}

__global__ void scan_phase1()
{
    __shared__ int ws[4];
    int i = blockIdx.x * 128 + threadIdx.x;
    int v = (i < N_NODES) ? g_deg[i] : 0;
    if (i < N_NODES) g_dinv[i] = rsqrtf((float)(v + 1));  // +1 self loop
    int lane = threadIdx.x & 31, wid = threadIdx.x >> 5;
    int s = v;
#pragma unroll
    for (int d = 16; d; d >>= 1) s += __shfl_xor_sync(0xffffffffu, s, d);
    if (lane == 0) ws[wid] = s;
    __syncthreads();
    if (threadIdx.x == 0) g_bsum[blockIdx.x] = ws[0] + ws[1] + ws[2] + ws[3];
}

__global__ void scan_phase23()
{
    __shared__ int ws[4];
    __shared__ int s_off;
    int i = blockIdx.x * 128 + threadIdx.x;
    int v = (i < N_NODES) ? g_deg[i] : 0;
    int lane = threadIdx.x & 31, wid = threadIdx.x >> 5;

    int part = 0;
    for (int j = threadIdx.x; j < blockIdx.x; j += 128) part += g_bsum[j];
#pragma unroll
    for (int d = 16; d; d >>= 1) part += __shfl_xor_sync(0xffffffffu, part, d);
    if (lane == 0) ws[wid] = part;
    __syncthreads();
    if (threadIdx.x == 0) s_off = ws[0] + ws[1] + ws[2] + ws[3];
    __syncthreads();
    int off = s_off;
    __syncthreads();  // ws reused below

    int s = v;
#pragma unroll
    for (int d = 1; d < 32; d <<= 1) {
        int n = __shfl_up_sync(0xffffffffu, s, d);
        if (lane >= d) s += n;
    }
    if (lane == 31) ws[wid] = s;
    __syncthreads();
    if (wid == 0 && lane < 4) {
        int w = ws[lane];
#pragma unroll
        for (int d = 1; d < 4; d <<= 1) {
            int n = __shfl_up_sync(0x0000000fu, w, d);
            if (lane >= d) w += n;
        }
        ws[lane] = w;
    }
    __syncthreads();
    if (i < N_NODES)
        g_rowptr[i] = off + (s - v) + (wid ? ws[wid - 1] : 0);
    if (blockIdx.x == NBLK - 1 && threadIdx.x == 127)
        g_rowptr[N_NODES] = off + ws[3];
}

__global__ void scatter_kernel(const void* __restrict__ ei)
{
    int e = blockIdx.x * blockDim.x + threadIdx.x;
    if (e >= E_EDGES) return;
    int s, d;
    if (g_is64) {
        const long long* p = (const long long*)ei;
        s = (int)p[e]; d = (int)p[E_EDGES + e];
    } else {
        const int* p = (const int*)ei;
        s = p[e]; d = p[E_EDGES + e];
    }
    int pos = g_rowptr[d] + atomicAdd(&g_cursor[d], 1);
    g_csr[pos] = make_int2(s, __float_as_int(g_dinv[s]));
}

// ---------------- layer 1 fused: scalar agg + expand + relu + dropout -> g_h(fp16) --
__global__ void aggx_expand_kernel(const float* __restrict__ x,
                                   const float* __restrict__ W0,
                                   const float* __restrict__ b0,
                                   uint32_t k0, uint32_t k1)
{
    int lane = threadIdx.x & 31;
    int node = (blockIdx.x * blockDim.x + threadIdx.x) >> 5;
    if (node >= N_NODES) return;
    int s = g_rowptr[node], e_end = g_rowptr[node + 1];
    float sum = 0.0f;
    for (int e = s + lane; e < e_end; e += 32) {
        int2 sw = __ldg(&g_csr[e]);
        sum = fmaf(__int_as_float(sw.y), __ldg(x + sw.x), sum);
    }
#pragma unroll
    for (int d = 16; d; d >>= 1) sum += __shfl_xor_sync(0xffffffffu, sum, d);
    float di = g_dinv[node];
    float a = di * fmaf(di, __ldg(x + node), sum);

    int j = lane * 8;
    float4 w0 = *(const float4*)(W0 + j);
    float4 w1 = *(const float4*)(W0 + j + 4);
    float4 bb0 = *(const float4*)(b0 + j);
    float4 bb1 = *(const float4*)(b0 + j + 4);
    uint32_t e0 = (uint32_t)(node * HID + j);
    float v0 = apply_dropout(fmaxf(fmaf(a, w0.x, bb0.x), 0.0f), k0, k1, e0 + 0);
    float v1 = apply_dropout(fmaxf(fmaf(a, w0.y, bb0.y), 0.0f), k0, k1, e0 + 1);
    float v2 = apply_dropout(fmaxf(fmaf(a, w0.z, bb0.z), 0.0f), k0, k1, e0 + 2);
    float v3 = apply_dropout(fmaxf(fmaf(a, w0.w, bb0.w), 0.0f), k0, k1, e0 + 3);
    float v4 = apply_dropout(fmaxf(fmaf(a, w1.x, bb1.x), 0.0f), k0, k1, e0 + 4);
    float v5 = apply_dropout(fmaxf(fmaf(a, w1.y, bb1.y), 0.0f), k0, k1, e0 + 5);
    float v6 = apply_dropout(fmaxf(fmaf(a, w1.z, bb1.z), 0.0f), k0, k1, e0 + 6);
    float v7 = apply_dropout(fmaxf(fmaf(a, w1.w, bb1.w), 0.0f), k0, k1, e0 + 7);
    __half2 h0 = __floats2half2_rn(v0, v1);
    __half2 h1 = __floats2half2_rn(v2, v3);
    __half2 h2 = __floats2half2_rn(v4, v5);
    __half2 h3 = __floats2half2_rn(v6, v7);
    *(uint4*)(g_h + node * HID + j) =
        make_uint4(*(uint32_t*)&h0, *(uint32_t*)&h1, *(uint32_t*)&h2, *(uint32_t*)&h3);
}

// ---------------- GEMM (HMMA + cp.async double buffer): g_t = g_h @ W ----------------
#define BK      32
#define AS_STR  40
#define BS_STR  136
__global__ void __launch_bounds__(256, 2) gemm_kernel(int wsel)
{
    const __half* __restrict__ W = wsel ? g_wh2 : g_wh1;
    __shared__ __half As[2][128 * AS_STR];
    __shared__ __half Bs[2][BK * BS_STR];
    int tid = threadIdx.x;
    int m0 = blockIdx.x * 128;
    int n0 = blockIdx.y * 128;
    int warp = tid >> 5, lane = tid & 31;
    int wm = warp & 3, wn = warp >> 2;

    float acc[2][8][4];
#pragma unroll
    for (int mt = 0; mt < 2; ++mt)
#pragma unroll
        for (int nt = 0; nt < 8; ++nt)
#pragma unroll
            for (int q = 0; q < 4; ++q) acc[mt][nt][q] = 0.0f;

    uint32_t as_base = (uint32_t)__cvta_generic_to_shared(As);
    uint32_t bs_base = (uint32_t)__cvta_generic_to_shared(Bs);

    int a_r0 = tid >> 2,  a_c0 = (tid & 3) * 8;
    int a_r1 = (tid + 256) >> 2, a_c1 = ((tid + 256) & 3) * 8;
    int b_r0 = tid >> 4,  b_c0 = (tid & 15) * 8;
    int b_r1 = (tid + 256) >> 4, b_c1 = ((tid + 256) & 15) * 8;

#define CP_TILE(kt, st)                                                                  \
    do {                                                                                 \
        cp16(as_base + (uint32_t)((st) * 128 * AS_STR + a_r0 * AS_STR + a_c0) * 2,       \
             g_h + (size_t)(m0 + a_r0) * HID + (kt) + a_c0);                             \
        cp16(as_base + (uint32_t)((st) * 128 * AS_STR + a_r1 * AS_STR + a_c1) * 2,       \
             g_h + (size_t)(m0 + a_r1) * HID + (kt) + a_c1);                             \
        cp16(bs_base + (uint32_t)((st) * BK * BS_STR + b_r0 * BS_STR + b_c0) * 2,        \
             W + (size_t)((kt) + b_r0) * HID + n0 + b_c0);                               \
        cp16(bs_base + (uint32_t)((st) * BK * BS_STR + b_r1 * BS_STR + b_c1) * 2,        \
             W + (size_t)((kt) + b_r1) * HID + n0 + b_c1);                               \
        asm volatile("cp.async.commit_group;");                                          \
    } while (0)

    CP_TILE(0, 0);

#pragma unroll
    for (int kti = 0; kti < HID / BK; ++kti) {
        int cur = kti & 1;
        if (kti < HID / BK - 1) CP_TILE((kti + 1) * BK, cur ^ 1);
        if (kti < HID / BK - 1) asm volatile("cp.async.wait_group 1;");
        else                    asm volatile("cp.async.wait_group 0;");
        __syncthreads();
        uint32_t a_off = as_base + (uint32_t)(cur * 128 * AS_STR) * 2;
        uint32_t b_off = bs_base + (uint32_t)(cur * BK * BS_STR) * 2;
#pragma unroll
        for (int ks = 0; ks < BK / 16; ++ks) {
            uint32_t a[2][4];
#pragma unroll
            for (int mt = 0; mt < 2; ++mt) {
                int row = wm * 32 + mt * 16 + (lane & 15);
                int col = ks * 16 + (lane >> 4) * 8;
                ldsm_x4(a[mt], a_off + (uint32_t)(row * AS_STR + col) * 2);
            }
#pragma unroll
            for (int nt = 0; nt < 8; ++nt) {
                uint32_t b[2];
                int brow = ks * 16 + (lane & 15);
                int bcol = wn * 64 + nt * 8;
                ldsm_x2_trans(b, b_off + (uint32_t)(brow * BS_STR + bcol) * 2);
                mma16816(acc[0][nt], a[0], b);
                mma16816(acc[1][nt], a[1], b);
            }
        }
        __syncthreads();
    }
#undef CP_TILE

    int g = lane >> 2, tig = lane & 3;
#pragma unroll
    for (int mt = 0; mt < 2; ++mt) {
#pragma unroll
        for (int nt = 0; nt < 8; ++nt) {
            int row = m0 + wm * 32 + mt * 16 + g;
            int col = n0 + wn * 64 + nt * 8 + tig * 2;
            __half2 h01 = __floats2half2_rn(acc[mt][nt][0], acc[mt][nt][1]);
            __half2 h23 = __floats2half2_rn(acc[mt][nt][2], acc[mt][nt][3]);
            *(__half2*)(g_t + (size_t)row * HID + col) = h01;
            *(__half2*)(g_t + (size_t)(row + 8) * HID + col) = h23;
        }
    }
}

// ---------------- shared agg core: gather + bias + relu + dropout -> o[8] ----------
__device__ __forceinline__ void agg_core(int node, int lane,
                                         const float* __restrict__ bias,
                                         uint32_t k0, uint32_t k1, float (&o)[8])
{
    int e = g_rowptr[node], e_end = g_rowptr[node + 1];
    float acc[8] = {0, 0, 0, 0, 0, 0, 0, 0};
    const uint4* T = (const uint4*)g_t;
    if (e < e_end) {
        int2 sw = __ldg(&g_csr[e]);
        uint4 v = __ldg(T + sw.x * (HID / 8) + lane);
        while (++e < e_end) {
            int2 sw_n = __ldg(&g_csr[e]);
            uint4 v_n = __ldg(T + sw_n.x * (HID / 8) + lane);
            float w = __int_as_float(sw.y);
            float2 f0 = __half22float2(*(__half2*)&v.x);
            float2 f1 = __half22float2(*(__half2*)&v.y);
            float2 f2 = __half22float2(*(__half2*)&v.z);
            float2 f3 = __half22float2(*(__half2*)&v.w);
            acc[0] = fmaf(w, f0.x, acc[0]); acc[1] = fmaf(w, f0.y, acc[1]);
            acc[2] = fmaf(w, f1.x, acc[2]); acc[3] = fmaf(w, f1.y, acc[3]);
            acc[4] = fmaf(w, f2.x, acc[4]); acc[5] = fmaf(w, f2.y, acc[5]);
            acc[6] = fmaf(w, f3.x, acc[6]); acc[7] = fmaf(w, f3.y, acc[7]);
            sw = sw_n; v = v_n;
        }
        float w = __int_as_float(sw.y);
        float2 f0 = __half22float2(*(__half2*)&v.x);
        float2 f1 = __half22float2(*(__half2*)&v.y);
        float2 f2 = __half22float2(*(__half2*)&v.z);
        float2 f3 = __half22float2(*(__half2*)&v.w);
        acc[0] = fmaf(w, f0.x, acc[0]); acc[1] = fmaf(w, f0.y, acc[1]);
        acc[2] = fmaf(w, f1.x, acc[2]); acc[3] = fmaf(w, f1.y, acc[3]);
        acc[4] = fmaf(w, f2.x, acc[4]); acc[5] = fmaf(w, f2.y, acc[5]);
        acc[6] = fmaf(w, f3.x, acc[6]); acc[7] = fmaf(w, f3.y, acc[7]);
    }
    float di = g_dinv[node];
    {   // self loop
        uint4 v = __ldg(T + node * (HID / 8) + lane);
        float2 f0 = __half22float2(*(__half2*)&v.x);
        float2 f1 = __half22float2(*(__half2*)&v.y);
        float2 f2 = __half22float2(*(__half2*)&v.z);
        float2 f3 = __half22float2(*(__half2*)&v.w);
        acc[0] = fmaf(di, f0.x, acc[0]); acc[1] = fmaf(di, f0.y, acc[1]);
        acc[2] = fmaf(di, f1.x, acc[2]); acc[3] = fmaf(di, f1.y, acc[3]);
        acc[4] = fmaf(di, f2.x, acc[4]); acc[5] = fmaf(di, f2.y, acc[5]);
        acc[6] = fmaf(di, f3.x, acc[6]); acc[7] = fmaf(di, f3.y, acc[7]);
    }
    float4 bb0 = *(const float4*)(bias + lane * 8);
    float4 bb1 = *(const float4*)(bias + lane * 8 + 4);
    o[0] = fmaxf(fmaf(acc[0], di, bb0.x), 0.0f);
    o[1] = fmaxf(fmaf(acc[1], di, bb0.y), 0.0f);
    o[2] = fmaxf(fmaf(acc[2], di, bb0.z), 0.0f);
    o[3] = fmaxf(fmaf(acc[3], di, bb0.w), 0.0f);
    o[4] = fmaxf(fmaf(acc[4], di, bb1.x), 0.0f);
    o[5] = fmaxf(fmaf(acc[5], di, bb1.y), 0.0f);
    o[6] = fmaxf(fmaf(acc[6], di, bb1.z), 0.0f);
    o[7] = fmaxf(fmaf(acc[7], di, bb1.w), 0.0f);
    uint32_t e0 = (uint32_t)(node * HID + lane * 8);
#pragma unroll
    for (int j = 0; j < 8; ++j)
        o[j] = apply_dropout(o[j], k0, k1, e0 + j);
}

// layer 2: agg -> g_h (fp16)
__global__ void agg_kernel(const float* __restrict__ bias, uint32_t k0, uint32_t k1)
{
    int lane = threadIdx.x & 31;
    int node = (blockIdx.x * blockDim.x + threadIdx.x) >> 5;
    if (node >= N_NODES) return;
    float o[8];
    agg_core(node, lane, bias, k0, k1, o);
    __half2 h0 = __floats2half2_rn(o[0], o[1]);
    __half2 h1 = __floats2half2_rn(o[2], o[3]);
    __half2 h2 = __floats2half2_rn(o[4], o[5]);
    __half2 h3 = __floats2half2_rn(o[6], o[7]);
    *(uint4*)(g_h + node * HID + lane * 8) =
        make_uint4(*(uint32_t*)&h0, *(uint32_t*)&h1, *(uint32_t*)&h2, *(uint32_t*)&h3);
}

// layer 3 fused with heads; Wq slice prefetched to smem via cp.async BEFORE the gather
// 128 threads = 4 warps/block; 4 x 8KB = 32KB static smem.
// smem layout interleaved [chunk j][lane]: uint4 index = warp*512 + j*32 + lane
__global__ void __launch_bounds__(128) agg_head_kernel(
    const float* __restrict__ bias, uint32_t k0, uint32_t k1,
    const float* __restrict__ Wq,
    const float* __restrict__ bq,
    float* __restrict__ out)
{
    __shared__ uint4 wq_s[4 * 512];
    int lane = threadIdx.x & 31;
    int w = threadIdx.x >> 5;
    int node = (blockIdx.x * 128 + threadIdx.x) >> 5;
    if (node >= N_NODES) return;

    // prefetch this node's Wq slice: lane copies 16 x 16B from its 256B segment
    const char* wq_g = (const char*)(Wq + (size_t)node * (HID * 8)) + lane * 256;
    uint32_t sdst = (uint32_t)__cvta_generic_to_shared(&wq_s[w * 512 + lane]);
#pragma unroll
    for (int j = 0; j < 16; ++j)
        cp16(sdst + (uint32_t)j * 32 * 16, wq_g + j * 16);
    asm volatile("cp.async.commit_group;");

    float o[8];
    agg_core(node, lane, bias, k0, k1, o);

    asm volatile("cp.async.wait_group 0;");
    // lane reads back only its own chunks -> no cross-lane sync needed
    const uint4* ws = &wq_s[w * 512 + lane];
    float q[8] = {0, 0, 0, 0, 0, 0, 0, 0};
#pragma unroll
    for (int j = 0; j < 16; ++j) {
        uint4 u = ws[j * 32];
        float s = o[j >> 1];
        const float* f = (const float*)&u;
        int p0 = (j & 1) * 4;
        q[p0 + 0] = fmaf(s, f[0], q[p0 + 0]);
        q[p0 + 1] = fmaf(s, f[1], q[p0 + 1]);
        q[p0 + 2] = fmaf(s, f[2], q[p0 + 2]);
        q[p0 + 3] = fmaf(s, f[3], q[p0 + 3]);
    }
#pragma unroll
    for (int d = 16; d; d >>= 1)
#pragma unroll
        for (int i = 0; i < 8; ++i)
            q[i] += __shfl_xor_sync(0xffffffffu, q[i], d);
    if (lane == 0) {
#pragma unroll
        for (int i = 0; i < 8; ++i)
            out[node * 8 + i] = q[i] + bq[node * 8 + i];
    }
}

// ---------------- launch ----------------
extern "C" void kernel_launch(void* const* d_in, const int* in_sizes, int n_in,
                              void* d_out, int out_size)
{
    const float* x  = (const float*)d_in[0];
    const void*  ei = d_in[1];
    const float* W0 = (const float*)d_in[2];
    const float* b0 = (const float*)d_in[3];
    const float* W1 = (const float*)d_in[4];
    const float* b1 = (const float*)d_in[5];
    const float* W2 = (const float*)d_in[6];
    const float* b2 = (const float*)d_in[7];
    const float* Wq = (const float*)d_in[8];
    const float* bq = (const float*)d_in[9];
    float* out = (float*)d_out;

    uint32_t dk[3][2];
    for (uint32_t i = 0; i < 3; ++i)
        threefry2x32(0u, 42u, 0u, i, &dk[i][0], &dk[i][1]);

    prep_kernel<<<144, 256>>>((const unsigned int*)ei, W1, W2);
    convert_kernel<<<(E_EDGES + 255) / 256, 256>>>(ei);
    scan_phase1<<<NBLK, 128>>>();
    scan_phase23<<<NBLK, 128>>>();
    scatter_kernel<<<(E_EDGES + 255) / 256, 256>>>(ei);

    aggx_expand_kernel<<<(N_NODES * 32 + 255) / 256, 256>>>(x, W0, b0, dk[0][0], dk[0][1]);

    gemm_kernel<<<dim3(NBLK, 2), 256>>>(0);
    agg_kernel<<<(N_NODES * 32 + 255) / 256, 256>>>(b1, dk[1][0], dk[1][1]);

    gemm_kernel<<<dim3(NBLK, 2), 256>>>(1);
    agg_head_kernel<<<(N_NODES * 4 * 32 + 127) / 128, 128>>>(b2, dk[2][0], dk[2][1], Wq, bq, out);
}

// round 13
// speedup vs baseline: 1.1384x; 1.1384x over previous
#include <cuda_runtime.h>
#include <cuda_fp16.h>
#include <stdint.h>

#define N_NODES 20000
#define NPAD    20096           // 157 * 128
#define NBLK    157             // NPAD / 128
#define HID     256
#define E_EDGES 640000
#define NH      (N_NODES * HID) // 5,120,000

// ---------------- scratch (device globals; no allocation) ----------------
__device__ int    g_is64;
__device__ int    g_deg[N_NODES];
__device__ int    g_cursor[N_NODES];    // seeded with rowptr by scan_phase23
__device__ int    g_rowptr[N_NODES + 1];
__device__ int    g_bsum[NBLK];
__device__ int2   g_csr[E_EDGES];       // (src, bitcast(dinv[src]))
__device__ float  g_dinv[N_NODES];
__device__ __half g_h[NPAD * HID];      // fp16 activations (pad rows stay zero)
__device__ __half g_t[NPAD * HID];      // fp16 GEMM output (gather payload)
__device__ __half g_wh1[HID * HID];     // fp16 weights
__device__ __half g_wh2[HID * HID];

// ---------------- mma/ldmatrix/cp.async helpers ----------------
__device__ __forceinline__ void ldsm_x4(uint32_t (&r)[4], uint32_t addr)
{
    asm volatile("ldmatrix.sync.aligned.m8n8.x4.shared.b16 {%0,%1,%2,%3}, [%4];"
        : "=r"(r[0]), "=r"(r[1]), "=r"(r[2]), "=r"(r[3]) : "r"(addr));
}
__device__ __forceinline__ void ldsm_x2_trans(uint32_t (&r)[2], uint32_t addr)
{
    asm volatile("ldmatrix.sync.aligned.m8n8.x2.trans.shared.b16 {%0,%1}, [%2];"
        : "=r"(r[0]), "=r"(r[1]) : "r"(addr));
}
__device__ __forceinline__ void mma16816(float (&c)[4], const uint32_t (&a)[4], const uint32_t (&b)[2])
{
    asm volatile("mma.sync.aligned.m16n8k16.row.col.f32.f16.f16.f32 "
        "{%0,%1,%2,%3}, {%4,%5,%6,%7}, {%8,%9}, {%0,%1,%2,%3};"
        : "+f"(c[0]), "+f"(c[1]), "+f"(c[2]), "+f"(c[3])
        : "r"(a[0]), "r"(a[1]), "r"(a[2]), "r"(a[3]), "r"(b[0]), "r"(b[1]));
}
__device__ __forceinline__ void cp16(uint32_t saddr, const void* g)
{
    asm volatile("cp.async.cg.shared.global [%0], [%1], 16;" :: "r"(saddr), "l"(g));
}

// ---------------- threefry2x32 (JAX-exact) ----------------
__host__ __device__ __forceinline__ void threefry2x32(
    uint32_t k0, uint32_t k1, uint32_t x0, uint32_t x1,
    uint32_t* o0, uint32_t* o1)
{
    uint32_t ks2 = k0 ^ k1 ^ 0x1BD11BDAu;
    x0 += k0; x1 += k1;
#define TF_R(r) { x0 += x1; x1 = (x1 << (r)) | (x1 >> (32 - (r))); x1 ^= x0; }
    TF_R(13) TF_R(15) TF_R(26) TF_R(6)
    x0 += k1; x1 += ks2 + 1u;
    TF_R(17) TF_R(29) TF_R(16) TF_R(24)
    x0 += ks2; x1 += k0 + 2u;
    TF_R(13) TF_R(15) TF_R(26) TF_R(6)
    x0 += k0; x1 += k1 + 3u;
    TF_R(17) TF_R(29) TF_R(16) TF_R(24)
    x0 += k1; x1 += ks2 + 4u;
    TF_R(13) TF_R(15) TF_R(26) TF_R(6)
    x0 += ks2; x1 += k0 + 5u;
#undef TF_R
    *o0 = x0; *o1 = x1;
}

// JAX partitionable threefry: bits32[e] = o0 ^ o1 at counter (0, e);
// keep <=> bit31 == 0; kept values scaled by 1/(1-p) = 2.
__device__ __forceinline__ float apply_dropout(float v, uint32_t k0, uint32_t k1, uint32_t e)
{
    uint32_t o0, o1;
    threefry2x32(k0, k1, 0u, e, &o0, &o1);
    return ((o0 ^ o1) & 0x80000000u) ? 0.0f : 2.0f * v;
}

// ---------------- prep: detect dtype + zero deg + convert weights ----------
__global__ void prep_kernel(const unsigned int* __restrict__ w,
                            const float* __restrict__ W1,
                            const float* __restrict__ W2)
{
    int b = blockIdx.x;
    if (b < 79) {
        int i = b * 256 + threadIdx.x;
        if (i < N_NODES) g_deg[i] = 0;
    } else if (b == 79) {
        if (threadIdx.x < 32) {
            int lane = threadIdx.x;
            int z = (w[4 * lane + 1] == 0u) && (w[4 * lane + 3] == 0u);
            unsigned m = __ballot_sync(0xffffffffu, z);
            if (lane == 0) g_is64 = (m == 0xffffffffu);
        }
    } else {
        int i = ((b - 80) * 256 + threadIdx.x) * 4;
        float4 v1 = *(const float4*)(W1 + i);
        float4 v2 = *(const float4*)(W2 + i);
        __half2 a1 = __floats2half2_rn(v1.x, v1.y), b1 = __floats2half2_rn(v1.z, v1.w);
        __half2 a2 = __floats2half2_rn(v2.x, v2.y), b2 = __floats2half2_rn(v2.z, v2.w);
        *(uint2*)(g_wh1 + i) = make_uint2(*(uint32_t*)&a1, *(uint32_t*)&b1);
        *(uint2*)(g_wh2 + i) = make_uint2(*(uint32_t*)&a2, *(uint32_t*)&b2);
    }
}

__global__ void convert_kernel(const void* __restrict__ ei)
{
    int e = blockIdx.x * blockDim.x + threadIdx.x;
    if (e >= E_EDGES) return;
    int d;
    if (g_is64) d = (int)((const long long*)ei)[E_EDGES + e];
    else        d = ((const int*)ei)[E_EDGES + e];
    atomicAdd(&g_deg[d], 1);
}

__global__ void scan_phase1()
{
    __shared__ int ws[4];
    int i = blockIdx.x * 128 + threadIdx.x;
    int v = (i < N_NODES) ? g_deg[i] : 0;
    if (i < N_NODES) g_dinv[i] = rsqrtf((float)(v + 1));  // +1 self loop
    int lane = threadIdx.x & 31, wid = threadIdx.x >> 5;
    int s = v;
#pragma unroll
    for (int d = 16; d; d >>= 1) s += __shfl_xor_sync(0xffffffffu, s, d);
    if (lane == 0) ws[wid] = s;
    __syncthreads();
    if (threadIdx.x == 0) g_bsum[blockIdx.x] = ws[0] + ws[1] + ws[2] + ws[3];
}

// local scan + block offset; also seeds g_cursor with rowptr
__global__ void scan_phase23()
{
    __shared__ int ws[4];
    __shared__ int s_off;
    int i = blockIdx.x * 128 + threadIdx.x;
    int v = (i < N_NODES) ? g_deg[i] : 0;
    int lane = threadIdx.x & 31, wid = threadIdx.x >> 5;

    int part = 0;
    for (int j = threadIdx.x; j < blockIdx.x; j += 128) part += g_bsum[j];
#pragma unroll
    for (int d = 16; d; d >>= 1) part += __shfl_xor_sync(0xffffffffu, part, d);
    if (lane == 0) ws[wid] = part;
    __syncthreads();
    if (threadIdx.x == 0) s_off = ws[0] + ws[1] + ws[2] + ws[3];
    __syncthreads();
    int off = s_off;
    __syncthreads();  // ws reused below

    int s = v;
#pragma unroll
    for (int d = 1; d < 32; d <<= 1) {
        int n = __shfl_up_sync(0xffffffffu, s, d);
        if (lane >= d) s += n;
    }
    if (lane == 31) ws[wid] = s;
    __syncthreads();
    if (wid == 0 && lane < 4) {
        int w = ws[lane];
#pragma unroll
        for (int d = 1; d < 4; d <<= 1) {
            int n = __shfl_up_sync(0x0000000fu, w, d);
            if (lane >= d) w += n;
        }
        ws[lane] = w;
    }
    __syncthreads();
    if (i < N_NODES) {
        int rp = off + (s - v) + (wid ? ws[wid - 1] : 0);
        g_rowptr[i] = rp;
        g_cursor[i] = rp;      // scatter bumps this directly
    }
    if (blockIdx.x == NBLK - 1 && threadIdx.x == 127)
        g_rowptr[N_NODES] = off + ws[3];
}

__global__ void scatter_kernel(const void* __restrict__ ei)
{
    int e = blockIdx.x * blockDim.x + threadIdx.x;
    if (e >= E_EDGES) return;
    int s, d;
    if (g_is64) {
        const long long* p = (const long long*)ei;
        s = (int)p[e]; d = (int)p[E_EDGES + e];
    } else {
        const int* p = (const int*)ei;
        s = p[e]; d = p[E_EDGES + e];
    }
    int pos = atomicAdd(&g_cursor[d], 1);   // cursor pre-seeded with rowptr
    g_csr[pos] = make_int2(s, __float_as_int(g_dinv[s]));
}

// ---------------- layer 1 fused: scalar agg + expand + relu + dropout -> g_h(fp16) --
__global__ void aggx_expand_kernel(const float* __restrict__ x,
                                   const float* __restrict__ W0,
                                   const float* __restrict__ b0,
                                   uint32_t k0, uint32_t k1)
{
    int lane = threadIdx.x & 31;
    int node = (blockIdx.x * blockDim.x + threadIdx.x) >> 5;
    if (node >= N_NODES) return;
    int s = g_rowptr[node], e_end = g_rowptr[node + 1];
    float sum = 0.0f;
    for (int e = s + lane; e < e_end; e += 32) {
        int2 sw = __ldg(&g_csr[e]);
        sum = fmaf(__int_as_float(sw.y), __ldg(x + sw.x), sum);
    }
#pragma unroll
    for (int d = 16; d; d >>= 1) sum += __shfl_xor_sync(0xffffffffu, sum, d);
    float di = g_dinv[node];
    float a = di * fmaf(di, __ldg(x + node), sum);

    int j = lane * 8;
    float4 w0 = *(const float4*)(W0 + j);
    float4 w1 = *(const float4*)(W0 + j + 4);
    float4 bb0 = *(const float4*)(b0 + j);
    float4 bb1 = *(const float4*)(b0 + j + 4);
    uint32_t e0 = (uint32_t)(node * HID + j);
    float v0 = apply_dropout(fmaxf(fmaf(a, w0.x, bb0.x), 0.0f), k0, k1, e0 + 0);
    float v1 = apply_dropout(fmaxf(fmaf(a, w0.y, bb0.y), 0.0f), k0, k1, e0 + 1);
    float v2 = apply_dropout(fmaxf(fmaf(a, w0.z, bb0.z), 0.0f), k0, k1, e0 + 2);
    float v3 = apply_dropout(fmaxf(fmaf(a, w0.w, bb0.w), 0.0f), k0, k1, e0 + 3);
    float v4 = apply_dropout(fmaxf(fmaf(a, w1.x, bb1.x), 0.0f), k0, k1, e0 + 4);
    float v5 = apply_dropout(fmaxf(fmaf(a, w1.y, bb1.y), 0.0f), k0, k1, e0 + 5);
    float v6 = apply_dropout(fmaxf(fmaf(a, w1.z, bb1.z), 0.0f), k0, k1, e0 + 6);
    float v7 = apply_dropout(fmaxf(fmaf(a, w1.w, bb1.w), 0.0f), k0, k1, e0 + 7);
    __half2 h0 = __floats2half2_rn(v0, v1);
    __half2 h1 = __floats2half2_rn(v2, v3);
    __half2 h2 = __floats2half2_rn(v4, v5);
    __half2 h3 = __floats2half2_rn(v6, v7);
    *(uint4*)(g_h + node * HID + j) =
        make_uint4(*(uint32_t*)&h0, *(uint32_t*)&h1, *(uint32_t*)&h2, *(uint32_t*)&h3);
}

// ---------------- GEMM (HMMA + cp.async double buffer): g_t = g_h @ W ----------------
#define BK      32
#define AS_STR  40
#define BS_STR  136
__global__ void __launch_bounds__(256, 2) gemm_kernel(int wsel)
{
    const __half* __restrict__ W = wsel ? g_wh2 : g_wh1;
    __shared__ __half As[2][128 * AS_STR];
    __shared__ __half Bs[2][BK * BS_STR];
    int tid = threadIdx.x;
    int m0 = blockIdx.x * 128;
    int n0 = blockIdx.y * 128;
    int warp = tid >> 5, lane = tid & 31;
    int wm = warp & 3, wn = warp >> 2;

    float acc[2][8][4];
#pragma unroll
    for (int mt = 0; mt < 2; ++mt)
#pragma unroll
        for (int nt = 0; nt < 8; ++nt)
#pragma unroll
            for (int q = 0; q < 4; ++q) acc[mt][nt][q] = 0.0f;

    uint32_t as_base = (uint32_t)__cvta_generic_to_shared(As);
    uint32_t bs_base = (uint32_t)__cvta_generic_to_shared(Bs);

    int a_r0 = tid >> 2,  a_c0 = (tid & 3) * 8;
    int a_r1 = (tid + 256) >> 2, a_c1 = ((tid + 256) & 3) * 8;
    int b_r0 = tid >> 4,  b_c0 = (tid & 15) * 8;
    int b_r1 = (tid + 256) >> 4, b_c1 = ((tid + 256) & 15) * 8;

#define CP_TILE(kt, st)                                                                  \
    do {                                                                                 \
        cp16(as_base + (uint32_t)((st) * 128 * AS_STR + a_r0 * AS_STR + a_c0) * 2,       \
             g_h + (size_t)(m0 + a_r0) * HID + (kt) + a_c0);                             \
        cp16(as_base + (uint32_t)((st) * 128 * AS_STR + a_r1 * AS_STR + a_c1) * 2,       \
             g_h + (size_t)(m0 + a_r1) * HID + (kt) + a_c1);                             \
        cp16(bs_base + (uint32_t)((st) * BK * BS_STR + b_r0 * BS_STR + b_c0) * 2,        \
             W + (size_t)((kt) + b_r0) * HID + n0 + b_c0);                               \
        cp16(bs_base + (uint32_t)((st) * BK * BS_STR + b_r1 * BS_STR + b_c1) * 2,        \
             W + (size_t)((kt) + b_r1) * HID + n0 + b_c1);                               \
        asm volatile("cp.async.commit_group;");                                          \
    } while (0)

    CP_TILE(0, 0);

#pragma unroll
    for (int kti = 0; kti < HID / BK; ++kti) {
        int cur = kti & 1;
        if (kti < HID / BK - 1) CP_TILE((kti + 1) * BK, cur ^ 1);
        if (kti < HID / BK - 1) asm volatile("cp.async.wait_group 1;");
        else                    asm volatile("cp.async.wait_group 0;");
        __syncthreads();
        uint32_t a_off = as_base + (uint32_t)(cur * 128 * AS_STR) * 2;
        uint32_t b_off = bs_base + (uint32_t)(cur * BK * BS_STR) * 2;
#pragma unroll
        for (int ks = 0; ks < BK / 16; ++ks) {
            uint32_t a[2][4];
#pragma unroll
            for (int mt = 0; mt < 2; ++mt) {
                int row = wm * 32 + mt * 16 + (lane & 15);
                int col = ks * 16 + (lane >> 4) * 8;
                ldsm_x4(a[mt], a_off + (uint32_t)(row * AS_STR + col) * 2);
            }
#pragma unroll
            for (int nt = 0; nt < 8; ++nt) {
                uint32_t b[2];
                int brow = ks * 16 + (lane & 15);
                int bcol = wn * 64 + nt * 8;
                ldsm_x2_trans(b, b_off + (uint32_t)(brow * BS_STR + bcol) * 2);
                mma16816(acc[0][nt], a[0], b);
                mma16816(acc[1][nt], a[1], b);
            }
        }
        __syncthreads();
    }
#undef CP_TILE

    int g = lane >> 2, tig = lane & 3;
#pragma unroll
    for (int mt = 0; mt < 2; ++mt) {
#pragma unroll
        for (int nt = 0; nt < 8; ++nt) {
            int row = m0 + wm * 32 + mt * 16 + g;
            int col = n0 + wn * 64 + nt * 8 + tig * 2;
            __half2 h01 = __floats2half2_rn(acc[mt][nt][0], acc[mt][nt][1]);
            __half2 h23 = __floats2half2_rn(acc[mt][nt][2], acc[mt][nt][3]);
            *(__half2*)(g_t + (size_t)row * HID + col) = h01;
            *(__half2*)(g_t + (size_t)(row + 8) * HID + col) = h23;
        }
    }
}

// ---------------- shared agg core: gather + bias + relu + dropout -> o[8] ----------
__device__ __forceinline__ void agg_core(int node, int lane,
                                         const float* __restrict__ bias,
                                         uint32_t k0, uint32_t k1, float (&o)[8])
{
    int e = g_rowptr[node], e_end = g_rowptr[node + 1];
    float acc[8] = {0, 0, 0, 0, 0, 0, 0, 0};
    const uint4* T = (const uint4*)g_t;
    if (e < e_end) {
        int2 sw = __ldg(&g_csr[e]);
        uint4 v = __ldg(T + sw.x * (HID / 8) + lane);
        while (++e < e_end) {
            int2 sw_n = __ldg(&g_csr[e]);
            uint4 v_n = __ldg(T + sw_n.x * (HID / 8) + lane);
            float w = __int_as_float(sw.y);
            float2 f0 = __half22float2(*(__half2*)&v.x);
            float2 f1 = __half22float2(*(__half2*)&v.y);
            float2 f2 = __half22float2(*(__half2*)&v.z);
            float2 f3 = __half22float2(*(__half2*)&v.w);
            acc[0] = fmaf(w, f0.x, acc[0]); acc[1] = fmaf(w, f0.y, acc[1]);
            acc[2] = fmaf(w, f1.x, acc[2]); acc[3] = fmaf(w, f1.y, acc[3]);
            acc[4] = fmaf(w, f2.x, acc[4]); acc[5] = fmaf(w, f2.y, acc[5]);
            acc[6] = fmaf(w, f3.x, acc[6]); acc[7] = fmaf(w, f3.y, acc[7]);
            sw = sw_n; v = v_n;
        }
        float w = __int_as_float(sw.y);
        float2 f0 = __half22float2(*(__half2*)&v.x);
        float2 f1 = __half22float2(*(__half2*)&v.y);
        float2 f2 = __half22float2(*(__half2*)&v.z);
        float2 f3 = __half22float2(*(__half2*)&v.w);
        acc[0] = fmaf(w, f0.x, acc[0]); acc[1] = fmaf(w, f0.y, acc[1]);
        acc[2] = fmaf(w, f1.x, acc[2]); acc[3] = fmaf(w, f1.y, acc[3]);
        acc[4] = fmaf(w, f2.x, acc[4]); acc[5] = fmaf(w, f2.y, acc[5]);
        acc[6] = fmaf(w, f3.x, acc[6]); acc[7] = fmaf(w, f3.y, acc[7]);
    }
    float di = g_dinv[node];
    {   // self loop
        uint4 v = __ldg(T + node * (HID / 8) + lane);
        float2 f0 = __half22float2(*(__half2*)&v.x);
        float2 f1 = __half22float2(*(__half2*)&v.y);
        float2 f2 = __half22float2(*(__half2*)&v.z);
        float2 f3 = __half22float2(*(__half2*)&v.w);
        acc[0] = fmaf(di, f0.x, acc[0]); acc[1] = fmaf(di, f0.y, acc[1]);
        acc[2] = fmaf(di, f1.x, acc[2]); acc[3] = fmaf(di, f1.y, acc[3]);
        acc[4] = fmaf(di, f2.x, acc[4]); acc[5] = fmaf(di, f2.y, acc[5]);
        acc[6] = fmaf(di, f3.x, acc[6]); acc[7] = fmaf(di, f3.y, acc[7]);
    }
    float4 bb0 = *(const float4*)(bias + lane * 8);
    float4 bb1 = *(const float4*)(bias + lane * 8 + 4);
    o[0] = fmaxf(fmaf(acc[0], di, bb0.x), 0.0f);
    o[1] = fmaxf(fmaf(acc[1], di, bb0.y), 0.0f);
    o[2] = fmaxf(fmaf(acc[2], di, bb0.z), 0.0f);
    o[3] = fmaxf(fmaf(acc[3], di, bb0.w), 0.0f);
    o[4] = fmaxf(fmaf(acc[4], di, bb1.x), 0.0f);
    o[5] = fmaxf(fmaf(acc[5], di, bb1.y), 0.0f);
    o[6] = fmaxf(fmaf(acc[6], di, bb1.z), 0.0f);
    o[7] = fmaxf(fmaf(acc[7], di, bb1.w), 0.0f);
    uint32_t e0 = (uint32_t)(node * HID + lane * 8);
#pragma unroll
    for (int j = 0; j < 8; ++j)
        o[j] = apply_dropout(o[j], k0, k1, e0 + j);
}

// layer 2: agg -> g_h (fp16)
__global__ void agg_kernel(const float* __restrict__ bias, uint32_t k0, uint32_t k1)
{
    int lane = threadIdx.x & 31;
    int node = (blockIdx.x * blockDim.x + threadIdx.x) >> 5;
    if (node >= N_NODES) return;
    float o[8];
    agg_core(node, lane, bias, k0, k1, o);
    __half2 h0 = __floats2half2_rn(o[0], o[1]);
    __half2 h1 = __floats2half2_rn(o[2], o[3]);
    __half2 h2 = __floats2half2_rn(o[4], o[5]);
    __half2 h3 = __floats2half2_rn(o[6], o[7]);
    *(uint4*)(g_h + node * HID + lane * 8) =
        make_uint4(*(uint32_t*)&h0, *(uint32_t*)&h1, *(uint32_t*)&h2, *(uint32_t*)&h3);
}

// layer 3 fused with heads (R11 version — 256 threads, direct Wq loads)
__global__ void agg_head_kernel(const float* __restrict__ bias, uint32_t k0, uint32_t k1,
                                const float* __restrict__ Wq,
                                const float* __restrict__ bq,
                                float* __restrict__ out)
{
    int lane = threadIdx.x & 31;
    int node = (blockIdx.x * blockDim.x + threadIdx.x) >> 5;
    if (node >= N_NODES) return;
    float o[8];
    agg_core(node, lane, bias, k0, k1, o);

    const float4* wrow = (const float4*)(Wq + (size_t)node * (HID * 8) + lane * 64);
    float q[8] = {0, 0, 0, 0, 0, 0, 0, 0};
#pragma unroll
    for (int j = 0; j < 8; ++j) {
        float s = o[j];
        float4 w0 = __ldg(wrow + j * 2);
        float4 w1 = __ldg(wrow + j * 2 + 1);
        q[0] = fmaf(s, w0.x, q[0]); q[1] = fmaf(s, w0.y, q[1]);
        q[2] = fmaf(s, w0.z, q[2]); q[3] = fmaf(s, w0.w, q[3]);
        q[4] = fmaf(s, w1.x, q[4]); q[5] = fmaf(s, w1.y, q[5]);
        q[6] = fmaf(s, w1.z, q[6]); q[7] = fmaf(s, w1.w, q[7]);
    }
#pragma unroll
    for (int d = 16; d; d >>= 1)
#pragma unroll
        for (int i = 0; i < 8; ++i)
            q[i] += __shfl_xor_sync(0xffffffffu, q[i], d);
    if (lane == 0) {
#pragma unroll
        for (int i = 0; i < 8; ++i)
            out[node * 8 + i] = q[i] + bq[node * 8 + i];
    }
}

// ---------------- launch ----------------
extern "C" void kernel_launch(void* const* d_in, const int* in_sizes, int n_in,
                              void* d_out, int out_size)
{
    const float* x  = (const float*)d_in[0];
    const void*  ei = d_in[1];
    const float* W0 = (const float*)d_in[2];
    const float* b0 = (const float*)d_in[3];
    const float* W1 = (const float*)d_in[4];
    const float* b1 = (const float*)d_in[5];
    const float* W2 = (const float*)d_in[6];
    const float* b2 = (const float*)d_in[7];
    const float* Wq = (const float*)d_in[8];
    const float* bq = (const float*)d_in[9];
    float* out = (float*)d_out;

    uint32_t dk[3][2];
    for (uint32_t i = 0; i < 3; ++i)
        threefry2x32(0u, 42u, 0u, i, &dk[i][0], &dk[i][1]);

    prep_kernel<<<144, 256>>>((const unsigned int*)ei, W1, W2);
    convert_kernel<<<(E_EDGES + 255) / 256, 256>>>(ei);
    scan_phase1<<<NBLK, 128>>>();
    scan_phase23<<<NBLK, 128>>>();
    scatter_kernel<<<(E_EDGES + 255) / 256, 256>>>(ei);

    aggx_expand_kernel<<<(N_NODES * 32 + 255) / 256, 256>>>(x, W0, b0, dk[0][0], dk[0][1]);

    gemm_kernel<<<dim3(NBLK, 2), 256>>>(0);
    agg_kernel<<<(N_NODES * 32 + 255) / 256, 256>>>(b1, dk[1][0], dk[1][1]);

    gemm_kernel<<<dim3(NBLK, 2), 256>>>(1);
    agg_head_kernel<<<(N_NODES * 32 + 255) / 256, 256>>>(b2, dk[2][0], dk[2][1], Wq, bq, out);
}